// round 16
// baseline (speedup 1.0000x reference)
#include <cuda_runtime.h>
#include <cuda_bf16.h>

#define D_DIM 64
#define LA_N  20
#define LC_N  5

__device__ __forceinline__ float dot4(float4 a, float4 b) {
    return a.x * b.x + a.y * b.y + a.z * b.z + a.w * b.w;
}

__global__ void __launch_bounds__(256)
aspect_kernel(const int* __restrict__ user_id,
              const int* __restrict__ artists_id,
              const int* __restrict__ categories_id,
              const float* __restrict__ user_factors,
              const float* __restrict__ entity_factors,
              const float* __restrict__ relation_k,
              float* __restrict__ out,
              int B)
{
    const unsigned FULL = 0xffffffffu;
    const int warp = (blockIdx.x * blockDim.x + threadIdx.x) >> 5;
    const int lane = threadIdx.x & 31;
    if (warp >= B) return;

    const int par = lane & 1;          // which entity of the pair this lane serves
    const int q   = (lane >> 1) * 4;   // first of 4 dims owned by this lane

    const int uid = user_id[warp];
    const float* urow = user_factors + (size_t)uid * D_DIM;
    const float4 u4 = *reinterpret_cast<const float4*>(urow + q);

    // ---- relation logits: u @ relation_k  (relation_k row-major [D,3]) ----
    // 12 consecutive floats starting at rk[q*3] = rows q..q+3, 16B-aligned.
    const float4* rkp = reinterpret_cast<const float4*>(relation_k + q * 3);
    const float4 f0 = rkp[0], f1 = rkp[1], f2 = rkp[2];
    float l0 = u4.x * f0.x + u4.y * f0.w + u4.z * f1.z + u4.w * f2.y;
    float l1 = u4.x * f0.y + u4.y * f1.x + u4.z * f1.w + u4.w * f2.z;
    float l2 = u4.x * f0.z + u4.y * f1.y + u4.z * f2.x + u4.w * f2.w;
    // parity-preserving butterfly: sums the 16 same-parity lanes = all 64 dims
    #pragma unroll
    for (int s = 16; s >= 2; s >>= 1) {
        l0 += __shfl_xor_sync(FULL, l0, s);
        l1 += __shfl_xor_sync(FULL, l1, s);
        l2 += __shfl_xor_sync(FULL, l2, s);
    }
    // both parity classes computed the same sums; no cross-parity fix needed
    l0 = (l0 > 0.f) ? l0 : 0.2f * l0;
    l1 = (l1 > 0.f) ? l1 : 0.2f * l1;
    l2 = (l2 > 0.f) ? l2 : 0.2f * l2;
    const float m   = fmaxf(l0, fmaxf(l1, l2));
    const float e0  = __expf(l0 - m);
    const float e1  = __expf(l1 - m);
    const float e2  = __expf(l2 - m);
    const float inv = 1.f / (e0 + e1 + e2);
    const float s_act = e0 * inv;
    const float s_dir = e1 * inv;
    const float s_2   = e2 * inv;

    // ---- artists: 20 dots, 2 entities per iteration (parity split) ----
    int myIdxA = (lane < LA_N) ? artists_id[warp * LA_N + lane] : 0;
    float preA = 0.f;
    #pragma unroll
    for (int it = 0; it < LA_N / 2; ++it) {
        const int e = __shfl_sync(FULL, myIdxA, 2 * it + par);
        const float4 v = *reinterpret_cast<const float4*>(
            entity_factors + (size_t)e * D_DIM + q);
        float d = dot4(u4, v);
        d += __shfl_xor_sync(FULL, d, 16);
        d += __shfl_xor_sync(FULL, d, 8);
        d += __shfl_xor_sync(FULL, d, 4);
        d += __shfl_xor_sync(FULL, d, 2);   // full dot of entity (2it+par)
        if (it == (lane >> 1)) preA = d;    // lane l parks entity l (l<20)
    }

    // ---- categories: 5 dots, 3 pair-iterations (last pair clamped) ----
    int myIdxC = (lane < LC_N) ? categories_id[warp * LC_N + lane] : 0;
    float preC = 0.f;
    #pragma unroll
    for (int it = 0; it < (LC_N + 1) / 2; ++it) {
        int slot = 2 * it + par;
        if (slot >= LC_N) slot = LC_N - 1;   // dup load, masked out below
        const int e = __shfl_sync(FULL, myIdxC, slot);
        const float4 v = *reinterpret_cast<const float4*>(
            entity_factors + (size_t)e * D_DIM + q);
        float d = dot4(u4, v);
        d += __shfl_xor_sync(FULL, d, 16);
        d += __shfl_xor_sync(FULL, d, 8);
        d += __shfl_xor_sync(FULL, d, 4);
        d += __shfl_xor_sync(FULL, d, 2);
        if (it == (lane >> 1)) preC = d;
    }

    // ---- means: one masked full butterfly each ----
    float sA = (lane < LA_N) ? preA : 0.f;
    float sC = (lane < LC_N) ? preC : 0.f;
    #pragma unroll
    for (int s = 16; s > 0; s >>= 1) {
        sA += __shfl_xor_sync(FULL, sA, s);
        sC += __shfl_xor_sync(FULL, sC, s);
    }
    const float c_act = sA * (1.f / LA_N);
    const float c_dir = sC * (1.f / LC_N);
    const float prediction = (c_act * s_act + c_dir * s_dir) / (s_act + s_dir);

    // ---- outputs: prediction[B] | scores[B,3] | c_act[B] | c_dir[B] |
    //               niubi_act[B,20] | niubi_dir[B,5]
    float* o_pred  = out;
    float* o_score = out + (size_t)B;
    float* o_cact  = out + (size_t)4 * B;
    float* o_cdir  = out + (size_t)5 * B;
    float* o_na    = out + (size_t)6 * B;
    float* o_nd    = out + (size_t)26 * B;

    if (lane == 0) {
        o_pred[warp] = prediction;
        o_cact[warp] = c_act;
        o_cdir[warp] = c_dir;
    }
    if (lane < 3) {
        const float sc = (lane == 0) ? s_act : (lane == 1) ? s_dir : s_2;
        o_score[warp * 3 + lane] = sc;
    }
    if (lane < LA_N) o_na[warp * LA_N + lane] = preA;
    if (lane < LC_N) o_nd[warp * LC_N + lane] = preC;
}

extern "C" void kernel_launch(void* const* d_in, const int* in_sizes, int n_in,
                              void* d_out, int out_size)
{
    int iU = 0, iA = 1, iC = 2, iUF, iEF, iRK;
    if (n_in >= 7) { iUF = 4; iEF = 5; iRK = 6; }
    else           { iUF = 3; iEF = 4; iRK = 5; }

    const int* user_id       = (const int*)d_in[iU];
    const int* artists_id    = (const int*)d_in[iA];
    const int* categories_id = (const int*)d_in[iC];
    const float* user_factors   = (const float*)d_in[iUF];
    const float* entity_factors = (const float*)d_in[iEF];
    const float* relation_k     = (const float*)d_in[iRK];
    float* out = (float*)d_out;

    const int B = in_sizes[iU];
    const int warps_per_block = 8;
    const int grid = (B + warps_per_block - 1) / warps_per_block;

    aspect_kernel<<<grid, warps_per_block * 32>>>(
        user_id, artists_id, categories_id,
        user_factors, entity_factors, relation_k, out, B);
}

// round 17
// speedup vs baseline: 1.4324x; 1.4324x over previous
#include <cuda_runtime.h>
#include <cuda_bf16.h>

#define D_DIM 64
#define LA_N  20
#define LC_N  5

__device__ __forceinline__ float dot4(float4 a, float4 b) {
    return a.x * b.x + a.y * b.y + a.z * b.z + a.w * b.w;
}

__global__ void __launch_bounds__(256)
aspect_kernel(const int* __restrict__ user_id,
              const int* __restrict__ artists_id,
              const int* __restrict__ categories_id,
              const float* __restrict__ user_factors,
              const float* __restrict__ entity_factors,
              const float* __restrict__ relation_k,
              float* __restrict__ out,
              int B)
{
    const unsigned FULL = 0xffffffffu;
    const int warp = (blockIdx.x * blockDim.x + threadIdx.x) >> 5;
    const int lane = threadIdx.x & 31;
    if (warp >= B) return;

    const int par = lane & 1;          // which entity of the pair this lane serves
    const int q   = (lane >> 1) * 4;   // first of 4 dims owned by this lane

    const int uid = user_id[warp];
    const float* urow = user_factors + (size_t)uid * D_DIM;
    const float4 u4 = *reinterpret_cast<const float4*>(urow + q);

    // ---- relation logits: u @ relation_k  (relation_k row-major [D,3]) ----
    // 12 consecutive floats starting at rk[q*3] = rows q..q+3, 16B-aligned.
    const float4* rkp = reinterpret_cast<const float4*>(relation_k + q * 3);
    const float4 f0 = rkp[0], f1 = rkp[1], f2 = rkp[2];
    float l0 = u4.x * f0.x + u4.y * f0.w + u4.z * f1.z + u4.w * f2.y;
    float l1 = u4.x * f0.y + u4.y * f1.x + u4.z * f1.w + u4.w * f2.z;
    float l2 = u4.x * f0.z + u4.y * f1.y + u4.z * f2.x + u4.w * f2.w;
    // parity-preserving butterfly: sums the 16 same-parity lanes = all 64 dims
    #pragma unroll
    for (int s = 16; s >= 2; s >>= 1) {
        l0 += __shfl_xor_sync(FULL, l0, s);
        l1 += __shfl_xor_sync(FULL, l1, s);
        l2 += __shfl_xor_sync(FULL, l2, s);
    }
    // both parity classes computed the same sums; no cross-parity fix needed
    l0 = (l0 > 0.f) ? l0 : 0.2f * l0;
    l1 = (l1 > 0.f) ? l1 : 0.2f * l1;
    l2 = (l2 > 0.f) ? l2 : 0.2f * l2;
    const float m   = fmaxf(l0, fmaxf(l1, l2));
    const float e0  = __expf(l0 - m);
    const float e1  = __expf(l1 - m);
    const float e2  = __expf(l2 - m);
    const float inv = 1.f / (e0 + e1 + e2);
    const float s_act = e0 * inv;
    const float s_dir = e1 * inv;
    const float s_2   = e2 * inv;

    // ---- artists: 20 dots, 2 entities per iteration (parity split) ----
    int myIdxA = (lane < LA_N) ? artists_id[warp * LA_N + lane] : 0;
    float preA = 0.f;
    #pragma unroll
    for (int it = 0; it < LA_N / 2; ++it) {
        const int e = __shfl_sync(FULL, myIdxA, 2 * it + par);
        const float4 v = *reinterpret_cast<const float4*>(
            entity_factors + (size_t)e * D_DIM + q);
        float d = dot4(u4, v);
        d += __shfl_xor_sync(FULL, d, 16);
        d += __shfl_xor_sync(FULL, d, 8);
        d += __shfl_xor_sync(FULL, d, 4);
        d += __shfl_xor_sync(FULL, d, 2);   // full dot of entity (2it+par)
        if (it == (lane >> 1)) preA = d;    // lane l parks entity l (l<20)
    }

    // ---- categories: 5 dots, 3 pair-iterations (last pair clamped) ----
    int myIdxC = (lane < LC_N) ? categories_id[warp * LC_N + lane] : 0;
    float preC = 0.f;
    #pragma unroll
    for (int it = 0; it < (LC_N + 1) / 2; ++it) {
        int slot = 2 * it + par;
        if (slot >= LC_N) slot = LC_N - 1;   // dup load, masked out below
        const int e = __shfl_sync(FULL, myIdxC, slot);
        const float4 v = *reinterpret_cast<const float4*>(
            entity_factors + (size_t)e * D_DIM + q);
        float d = dot4(u4, v);
        d += __shfl_xor_sync(FULL, d, 16);
        d += __shfl_xor_sync(FULL, d, 8);
        d += __shfl_xor_sync(FULL, d, 4);
        d += __shfl_xor_sync(FULL, d, 2);
        if (it == (lane >> 1)) preC = d;
    }

    // ---- means: one masked full butterfly each ----
    float sA = (lane < LA_N) ? preA : 0.f;
    float sC = (lane < LC_N) ? preC : 0.f;
    #pragma unroll
    for (int s = 16; s > 0; s >>= 1) {
        sA += __shfl_xor_sync(FULL, sA, s);
        sC += __shfl_xor_sync(FULL, sC, s);
    }
    const float c_act = sA * (1.f / LA_N);
    const float c_dir = sC * (1.f / LC_N);
    const float prediction = (c_act * s_act + c_dir * s_dir) / (s_act + s_dir);

    // ---- outputs: prediction[B] | scores[B,3] | c_act[B] | c_dir[B] |
    //               niubi_act[B,20] | niubi_dir[B,5]
    float* o_pred  = out;
    float* o_score = out + (size_t)B;
    float* o_cact  = out + (size_t)4 * B;
    float* o_cdir  = out + (size_t)5 * B;
    float* o_na    = out + (size_t)6 * B;
    float* o_nd    = out + (size_t)26 * B;

    if (lane == 0) {
        o_pred[warp] = prediction;
        o_cact[warp] = c_act;
        o_cdir[warp] = c_dir;
    }
    if (lane < 3) {
        const float sc = (lane == 0) ? s_act : (lane == 1) ? s_dir : s_2;
        o_score[warp * 3 + lane] = sc;
    }
    if (lane < LA_N) o_na[warp * LA_N + lane] = preA;
    if (lane < LC_N) o_nd[warp * LC_N + lane] = preC;
}

extern "C" void kernel_launch(void* const* d_in, const int* in_sizes, int n_in,
                              void* d_out, int out_size)
{
    int iU = 0, iA = 1, iC = 2, iUF, iEF, iRK;
    if (n_in >= 7) { iUF = 4; iEF = 5; iRK = 6; }
    else           { iUF = 3; iEF = 4; iRK = 5; }

    const int* user_id       = (const int*)d_in[iU];
    const int* artists_id    = (const int*)d_in[iA];
    const int* categories_id = (const int*)d_in[iC];
    const float* user_factors   = (const float*)d_in[iUF];
    const float* entity_factors = (const float*)d_in[iEF];
    const float* relation_k     = (const float*)d_in[iRK];
    float* out = (float*)d_out;

    const int B = in_sizes[iU];
    const int warps_per_block = 8;
    const int grid = (B + warps_per_block - 1) / warps_per_block;

    aspect_kernel<<<grid, warps_per_block * 32>>>(
        user_id, artists_id, categories_id,
        user_factors, entity_factors, relation_k, out, B);
}